// round 14
// baseline (speedup 1.0000x reference)
#include <cuda_runtime.h>

// Fixed shapes
#define HH 96
#define WW 160
#define CC 100
#define hH 48
#define hW 80
#define MD 9
#define KD 19
#define K2 361
#define K2P 364          // padded stride for float4-aligned S rows

// int8 path
#define CP8 112          // channels padded to 112 int8 (7 x 16B chunks)
#define QSCALE 32.0f
#define QSCALE2_INV (1.0f/1024.0f)
// d >= 20 -> (sigmoid(d)-0.5)*2 rounds to 1.0f in fp32 (true already at ~18)
#define DSAT_I (20*1024)

// dist tiling
#define PR 2
#define PC 4
#define TROWS (PR + 2*MD)   // 20
#define TCOLS (PC + 2*MD)   // 22
#define TPITCH 28           // uint4 pitch -> conflict-free 8-lane LDS.128 phases
#define TPOS (TROWS*TCOLS)  // 440
#define KHALF 192           // k-slots per z-half

// scratch (device globals; allocation is forbidden)
__device__ __align__(16) signed char g_yq[hH*hW*CP8];
__device__ int g_syq[hH*hW];
__device__ __align__(16) float g_S[hH*hW*K2P];
__device__ int g_minS[hH*hW];     // per-pixel min over k of S (float bits as int)

// ---------------------------------------------------------------------------
// cp.async helpers (LDGSTS). src_size=0 -> zero fill (OOB handling).
__device__ __forceinline__ void cp_async16(void* dst, const void* src, int sz) {
    unsigned d = (unsigned)__cvta_generic_to_shared(dst);
    asm volatile("cp.async.ca.shared.global [%0], [%1], 16, %2;\n"
                 :: "r"(d), "l"(src), "r"(sz) : "memory");
}
__device__ __forceinline__ void cp_async4(void* dst, const void* src, int sz) {
    unsigned d = (unsigned)__cvta_generic_to_shared(dst);
    asm volatile("cp.async.ca.shared.global [%0], [%1], 4, %2;\n"
                 :: "r"(d), "l"(src), "r"(sz) : "memory");
}
__device__ __forceinline__ void cp_commit() { asm volatile("cp.async.commit_group;\n" ::: "memory"); }
template<int M> __device__ __forceinline__ void cp_wait() {
    asm volatile("cp.async.wait_group %0;\n" :: "n"(M) : "memory");
}
__device__ __forceinline__ void dp8(int& a, uint4 x, uint4 y) {
    a = __dp4a((int)x.x, (int)y.x, a);
    a = __dp4a((int)x.y, (int)y.y, a);
    a = __dp4a((int)x.z, (int)y.z, a);
    a = __dp4a((int)x.w, (int)y.w, a);
}

// ---------------------------------------------------------------------------
// Kernel A: 2x2 avg-pool + int8 quantize of PREV only (query pooled in dist).
// Warp per half-res pixel: 480 blocks x 256 threads. Also inits g_minS.
// ---------------------------------------------------------------------------
__global__ __launch_bounds__(256) void kern_down(const float* __restrict__ prev) {
    int pixel = blockIdx.x * 8 + (threadIdx.x >> 5);
    int lane  = threadIdx.x & 31;
    int r = pixel / hW, c = pixel - r*hW;
    int ch0 = lane * 4;

    float4 ys = make_float4(0.f,0.f,0.f,0.f);
    if (lane < 25) {
        int b = ((2*r)*WW + 2*c)*CC + ch0;
        float4 p0 = *(const float4*)&prev[b];
        float4 p1 = *(const float4*)&prev[b + CC];
        float4 p2 = *(const float4*)&prev[b + WW*CC];
        float4 p3 = *(const float4*)&prev[b + WW*CC + CC];
        ys = make_float4(0.25f*(p0.x+p1.x+p2.x+p3.x), 0.25f*(p0.y+p1.y+p2.y+p3.y),
                         0.25f*(p0.z+p1.z+p2.z+p3.z), 0.25f*(p0.w+p1.w+p2.w+p3.w));
    }
    float vy[4] = {ys.x, ys.y, ys.z, ys.w};
    int qy[4];
    int sy = 0;
    #pragma unroll
    for (int t = 0; t < 4; t++) {
        int b = __float2int_rn(vy[t] * QSCALE); b = max(-127, min(127, b));
        qy[t] = b;
        sy += b*b;
    }
    if (lane < 28) {
        *(char4*)&g_yq[pixel*CP8 + ch0] = make_char4((char)qy[0],(char)qy[1],(char)qy[2],(char)qy[3]);
    }
    sy = __reduce_add_sync(0xffffffffu, sy);
    if (lane == 0) { g_syq[pixel] = sy; g_minS[pixel] = 0x3F800000; }  // 1.0f bits

    cudaTriggerProgrammaticLaunchCompletion();
}

// ---------------------------------------------------------------------------
// Kernel B: k-split across blockIdx.z (2 halves x 192 k-slots). Pools its own
// x tile PRE-SYNC (overlaps kern_down via PDL), then int8 dp4a distances with
// cp.async ping-pong staging of y. pix = tid&7, kg = tid>>3, 6 k per thread.
// Halved per-thread state -> fewer regs -> higher occupancy (R9: 114r/22%occ).
// Per-pixel min goes to g_minS via global atomicMin (fires only when val<1).
// ---------------------------------------------------------------------------
__global__ __launch_bounds__(256) void kern_dist(const float* __restrict__ query) {
    __shared__ __align__(16) uint4 ysP[2][2][TROWS*TPITCH];
    __shared__ int sy_s[TPOS];
    __shared__ __align__(16) signed char x_s[8*CP8];
    __shared__ int sx_s[8];

    int tid = threadIdx.x;
    int warp = tid >> 5;
    int lane = tid & 31;
    int pix = tid & 7;
    int kg  = tid >> 3;                  // 0..31
    int pr  = pix >> 2, pc = pix & 3;
    int r0 = blockIdx.y * PR, c0 = blockIdx.x * PC;
    int r = r0 + pr, c = c0 + pc;
    int kbase = blockIdx.z * KHALF + kg; // k = kbase + 32*j, j<6
    bool j5ok = (blockIdx.z == 0) || (kg < 9);   // half1 j=5: k=352+kg<361

    // ---- PRE-SYNC: pool + quantize x for this block's 8 pixels (query input)
    {
        int wpr = warp >> 2, wpc = warp & 3;
        int rr = r0 + wpr, cc = c0 + wpc;
        int ch0 = lane * 4;
        float4 xs = make_float4(0.f,0.f,0.f,0.f);
        if (lane < 25) {
            int b = ((2*rr)*WW + 2*cc)*CC + ch0;
            float4 q0 = *(const float4*)&query[b];
            float4 q1 = *(const float4*)&query[b + CC];
            float4 q2 = *(const float4*)&query[b + WW*CC];
            float4 q3 = *(const float4*)&query[b + WW*CC + CC];
            xs = make_float4(0.25f*(q0.x+q1.x+q2.x+q3.x), 0.25f*(q0.y+q1.y+q2.y+q3.y),
                             0.25f*(q0.z+q1.z+q2.z+q3.z), 0.25f*(q0.w+q1.w+q2.w+q3.w));
        }
        float vx[4] = {xs.x, xs.y, xs.z, xs.w};
        int qx[4];
        int sx = 0;
        #pragma unroll
        for (int t = 0; t < 4; t++) {
            int a = __float2int_rn(vx[t] * QSCALE); a = max(-127, min(127, a));
            qx[t] = a;
            sx += a*a;
        }
        if (lane < 28)
            *(char4*)&x_s[warp*CP8 + ch0] = make_char4((char)qx[0],(char)qx[1],(char)qx[2],(char)qx[3]);
        sx = __reduce_add_sync(0xffffffffu, sx);
        if (lane == 0) sx_s[warp] = sx;
    }

    // pre-sync index math
    int soff[6];
    #pragma unroll
    for (int j = 0; j < 6; j++) {
        int k = kbase + 32*j;
        int dy = k / KD;
        int dx = k - dy*KD;
        soff[j] = (pr + dy)*TPITCH + (pc + dx);
    }

    int dsti[2], pos[2], sz[2];
    long srcoff[2];
    bool has[2] = {true, (tid + 256) < TPOS};
    #pragma unroll
    for (int s = 0; s < 2; s++) {
        int i = tid + 256*s;
        int ii = has[s] ? i : 0;
        int row = ii / TCOLS, col = ii - row*TCOLS;
        int gr = r0 - MD + row, gc = c0 - MD + col;
        bool ok = (unsigned)gr < hH && (unsigned)gc < hW;
        pos[s]  = ii;
        dsti[s] = row*TPITCH + col;
        srcoff[s] = ok ? (long)(gr*hW + gc)*CP8 : 0;
        sz[s] = ok ? 16 : 0;
    }

    cudaGridDependencySynchronize();    // g_yq/g_syq/g_minS ready

    const uint4* xg = reinterpret_cast<const uint4*>(&x_s[pix*CP8]);

    int acc[6];
    #pragma unroll
    for (int j = 0; j < 6; j++) acc[j] = 0;

    #define STAGE_PAIR(base, A, B)                                         \
        _Pragma("unroll")                                                  \
        for (int s = 0; s < 2; s++) if (has[s]) {                          \
            const signed char* p = g_yq + srcoff[s] + (base)*16;           \
            cp_async16(&(A)[dsti[s]], p, sz[s]);                           \
            cp_async16(&(B)[dsti[s]], p + 16, sz[s]);                      \
        }

    #define COMP_PAIR(A, B, base)                                          \
        {                                                                  \
            uint4 xa = xg[base], xb = xg[(base)+1];                        \
            _Pragma("unroll")                                              \
            for (int j = 0; j < 5; j++) {                                  \
                uint4 ya = (A)[soff[j]];                                   \
                uint4 yb = (B)[soff[j]];                                   \
                dp8(acc[j], xa, ya); dp8(acc[j], xb, yb);                  \
            }                                                              \
            if (j5ok) {                                                    \
                uint4 ya = (A)[soff[5]];                                   \
                uint4 yb = (B)[soff[5]];                                   \
                dp8(acc[5], xa, ya); dp8(acc[5], xb, yb);                  \
            }                                                              \
        }

    STAGE_PAIR(0, ysP[0][0], ysP[0][1]); cp_commit();
    STAGE_PAIR(2, ysP[1][0], ysP[1][1]); cp_commit();
    cp_wait<1>(); __syncthreads();     // also publishes x_s / sx_s
    COMP_PAIR(ysP[0][0], ysP[0][1], 0);
    __syncthreads();
    STAGE_PAIR(4, ysP[0][0], ysP[0][1]); cp_commit();
    cp_wait<1>(); __syncthreads();
    COMP_PAIR(ysP[1][0], ysP[1][1], 2);
    __syncthreads();
    #pragma unroll
    for (int s = 0; s < 2; s++) if (has[s]) {
        const signed char* p = g_yq + srcoff[s] + 96;
        cp_async16(&ysP[1][0][dsti[s]], p, sz[s]);
        const int* ps = g_syq + (srcoff[s] / CP8);
        cp_async4(&sy_s[pos[s]], ps, sz[s] ? 4 : 0);
    }
    cp_commit();
    cp_wait<1>(); __syncthreads();
    COMP_PAIR(ysP[0][0], ysP[0][1], 4);
    __syncthreads();
    cp_wait<0>(); __syncthreads();
    {
        uint4 xa = xg[6];
        #pragma unroll
        for (int j = 0; j < 5; j++) { uint4 ya = ysP[1][0][soff[j]]; dp8(acc[j], xa, ya); }
        if (j5ok)                   { uint4 ya = ysP[1][0][soff[5]]; dp8(acc[5], xa, ya); }
    }

    int sx = sx_s[pix];
    float* Srow = &g_S[(r*hW + c)*K2P];
    float vmin = 1.0f;
    #pragma unroll
    for (int j = 0; j < 6; j++) {
        int k = kbase + 32*j;
        if (k < K2P) {
            float val = 1.0f;   // PAD / out-of-range -> saturated sigmoid
            if (k < K2) {
                int dy = k / KD, dx = k - dy*KD;
                int sr = r + dy - MD, sc = c + dx - MD;
                if (sr >= 0 && sr < hH && sc >= 0 && sc < hW) {
                    int di = sx + sy_s[(pr + dy)*TCOLS + (pc + dx)] - 2*acc[j];
                    if (di < DSAT_I) {   // else saturates to exactly 1.0f
                        float d = (float)di * QSCALE2_INV;
                        float e = __expf(-d);
                        val = (1.0f - e) / (1.0f + e);   // == (sigmoid(d)-0.5)*2
                        vmin = fminf(vmin, val);
                    }
                }
            }
            Srow[k] = val;
        }
    }
    // per-pixel min (positive floats: int compare == float compare); rare.
    if (vmin < 1.0f) atomicMin(&g_minS[r*hW + c], __float_as_int(vmin));

    #undef STAGE_PAIR
    #undef COMP_PAIR
    cudaTriggerProgrammaticLaunchCompletion();
}

// ---------------------------------------------------------------------------
// Kernel C: bilinear upsample + per-object masked min.
// Block = 16 output pixels of one row (512 threads, warp per pixel).
// BLOCK FAST PATH: if min over the block's 2x10 staged S rows (via g_minS)
// is 1.0, every lerp and masked min is exactly 1.0 -> write 1.0s and exit
// before any staging. Exact for any input; triggers ~always when saturated.
// ---------------------------------------------------------------------------
#define OPX 16
#define NW 10
#define LROWS KD            // 19
#define LCOLS (OPX + 2*MD)  // 34
template<int N>
__global__ __launch_bounds__(512) void kern_out(const int* __restrict__ labels,
                                                const int* __restrict__ gt,
                                                float* __restrict__ out) {
    __shared__ __align__(16) float Rv[NW][K2P];
    __shared__ int lab[LROWS*LCOLS];
    __shared__ int fastflag;

    int tid  = threadIdx.x;
    int warp = tid >> 5;
    int lane = tid & 31;
    int Y     = blockIdx.y;
    int Xbase = blockIdx.x * OPX;

    // ---- pre-sync: labels (input) + index math ----
    for (int i = tid; i < LROWS*LCOLS; i += 512) {
        int row = i / LCOLS, col = i - row*LCOLS;
        int gr = Y - MD + row, gc = Xbase - MD + col;
        lab[i] = (gr >= 0 && gr < HH && gc >= 0 && gc < WW) ? labels[gr*WW + gc] : -1;
    }

    const float sH = (float)(47.0/95.0);
    const float sW = (float)(79.0/159.0);
    float pH = (float)Y * sH;
    int loH = (int)floorf(pH); if (loH > hH-2) loH = hH-2;
    float fH = pH - (float)loH;
    int lo_min = (int)floorf((float)Xbase * sW);

    int X = Xbase + warp;
    float pW = (float)X * sW;
    int loW = (int)floorf(pW); if (loW > hW-2) loW = hW-2;
    float fW = pW - (float)loW;
    int wl = loW - lo_min;      // 0..8

    int gid[N];
    #pragma unroll
    for (int nn = 0; nn < N; nn++) gid[nn] = gt[nn];
    float mv[N];
    #pragma unroll
    for (int nn = 0; nn < N; nn++) mv[nn] = 1.0f;

    cudaGridDependencySynchronize();     // g_S / g_minS ready (PDL)

    // ---- block fast-path check: min over the 2 x NW relevant minS entries ----
    if (warp == 0) {
        float v = 1.0f;
        if (lane < 2*NW) {
            int rr = lane / NW, ccol = lane - rr*NW;
            int w = lo_min + ccol; if (w > hW-1) w = hW-1;
            v = __int_as_float(g_minS[(loH + rr)*hW + w]);
        }
        #pragma unroll
        for (int o = 16; o; o >>= 1) v = fminf(v, __shfl_xor_sync(0xffffffffu, v, o));
        if (lane == 0) fastflag = (v >= 1.0f);
    }
    __syncthreads();

    if (fastflag) {
        if (tid < OPX*N) {
            int p  = tid / N;
            int nn = tid - p*N;
            out[(Y*WW + Xbase + p)*N + nn] = 1.0f;
        }
        return;
    }

    // ---- slow path: stage with fused vertical lerp ----
    for (int i = tid; i < NW*(K2P/4); i += 512) {
        int ccol = i / (K2P/4);
        int qq   = i - ccol*(K2P/4);
        int w = lo_min + ccol; if (w > hW-1) w = hW-1;
        float4 a = ((const float4*)&g_S[(loH*hW + w)*K2P])[qq];
        float4 b = ((const float4*)&g_S[((loH+1)*hW + w)*K2P])[qq];
        float4 rr;
        rr.x = a.x + fH*(b.x - a.x);
        rr.y = a.y + fH*(b.y - a.y);
        rr.z = a.z + fH*(b.z - a.z);
        rr.w = a.w + fH*(b.w - a.w);
        ((float4*)Rv[0])[ccol*(K2P/4) + qq] = rr;
    }
    __syncthreads();

    // ---- per-warp horizontal lerp + masked min, with group saturation skip ----
    const float* Ra = Rv[wl];
    const float* Rb = Rv[wl+1];
    #pragma unroll
    for (int it = 0; it < 3; it++) {
        int q = lane + 32*it;
        if (q < 91) {
            float4 a = *(const float4*)&Ra[4*q];
            float4 b = *(const float4*)&Rb[4*q];
            float gm = fminf(fminf(fminf(a.x,a.y), fminf(a.z,a.w)),
                             fminf(fminf(b.x,b.y), fminf(b.z,b.w)));
            if (gm < 1.0f) {
                float av[4] = {a.x,a.y,a.z,a.w};
                float bv[4] = {b.x,b.y,b.z,b.w};
                #pragma unroll
                for (int t = 0; t < 4; t++) {
                    int k = 4*q + t;
                    if (k < K2) {
                        int dy = k / KD, dx = k - dy*KD;
                        int lbl = lab[dy*LCOLS + warp + dx];
                        float dval = av[t] + fW*(bv[t] - av[t]);
                        #pragma unroll
                        for (int nn = 0; nn < N; nn++)
                            if (lbl == gid[nn]) mv[nn] = fminf(mv[nn], dval);
                    }
                }
            }
        }
    }
    #pragma unroll
    for (int nn = 0; nn < N; nn++) {
        float v = mv[nn];
        #pragma unroll
        for (int o = 16; o; o >>= 1) v = fminf(v, __shfl_xor_sync(0xffffffffu, v, o));
        if (lane == 0) out[(Y*WW + X)*N + nn] = v;
    }
}

// ---------------------------------------------------------------------------
static void launch_pdl_raw(void* func, dim3 grid, dim3 block, void** args) {
    cudaLaunchConfig_t cfg = {};
    cudaLaunchAttribute attr[1];
    attr[0].id = cudaLaunchAttributeProgrammaticStreamSerialization;
    attr[0].val.programmaticStreamSerializationAllowed = 1;
    cfg.gridDim  = grid;
    cfg.blockDim = block;
    cfg.attrs = attr;
    cfg.numAttrs = 1;
    cfg.stream = 0;
    cudaLaunchKernelExC(&cfg, func, args);
}

template<int N>
static void launch_out_pdl(const int* labels, const int* gt, float* out) {
    void* args[] = {(void*)&labels, (void*)&gt, (void*)&out};
    launch_pdl_raw((void*)kern_out<N>, dim3(WW/OPX, HH, 1), dim3(512,1,1), args);
}

extern "C" void kernel_launch(void* const* d_in, const int* in_sizes, int n_in,
                              void* d_out, int out_size) {
    const float* prev   = (const float*)d_in[0];
    const float* query  = (const float*)d_in[1];
    const int*   labels = (const int*)d_in[2];
    const int*   gt     = (const int*)d_in[3];
    float* out = (float*)d_out;
    int n = out_size / (HH*WW);

    kern_down<<<hH*hW/8, 256>>>(prev);            // 480 blocks

    {   // kern_dist with PDL (k split across z: 960 blocks)
        void* args[] = {(void*)&query};
        launch_pdl_raw((void*)kern_dist, dim3(hW/PC, hH/PR, 2), dim3(256,1,1), args);
    }
    switch (n) {
        case 1: launch_out_pdl<1>(labels, gt, out); break;
        case 2: launch_out_pdl<2>(labels, gt, out); break;
        case 3: launch_out_pdl<3>(labels, gt, out); break;
        case 4: launch_out_pdl<4>(labels, gt, out); break;
        case 5: launch_out_pdl<5>(labels, gt, out); break;
        case 6: launch_out_pdl<6>(labels, gt, out); break;
        case 7: launch_out_pdl<7>(labels, gt, out); break;
        default: launch_out_pdl<8>(labels, gt, out); break;
    }
}

// round 15
// speedup vs baseline: 1.1707x; 1.1707x over previous
#include <cuda_runtime.h>

// Fixed shapes
#define HH 96
#define WW 160
#define CC 100
#define hH 48
#define hW 80
#define MD 9
#define KD 19
#define K2 361
#define K2P 364          // padded stride for float4-aligned S rows

// int8 path
#define CP8 112          // channels padded to 112 int8 (7 x 16B chunks)
#define QSCALE 32.0f
#define QSCALE2_INV (1.0f/1024.0f)
// d >= 20 -> (sigmoid(d)-0.5)*2 rounds to 1.0f in fp32 (true already at ~18)
#define DSAT_I (20*1024)

// dist tiling
#define PR 2
#define PC 4
#define TROWS (PR + 2*MD)   // 20
#define TCOLS (PC + 2*MD)   // 22
#define TPITCH 28           // uint4 pitch -> conflict-free 8-lane LDS.128 phases
#define TPOS (TROWS*TCOLS)  // 440
#define STGB (TROWS*TPITCH*16)          // bytes per staged chunk array (8960)
#define DSM_SY   (7*STGB)               // 62720
#define DSM_XS   (DSM_SY + TPOS*4)      // 64480
#define DSM_SXS  (DSM_XS + 8*CP8)       // 65376
#define DSM_TOT  (DSM_SXS + 32)         // 65408 bytes dynamic smem

// scratch (device globals; allocation is forbidden)
__device__ __align__(16) signed char g_yq[hH*hW*CP8];
__device__ int g_syq[hH*hW];
__device__ __align__(16) float g_S[hH*hW*K2P];
__device__ int g_minS[hH*hW];     // per-pixel min over k of S (float bits)

// ---------------------------------------------------------------------------
// cp.async helpers (LDGSTS). src_size=0 -> zero fill (OOB handling).
__device__ __forceinline__ void cp_async16(void* dst, const void* src, int sz) {
    unsigned d = (unsigned)__cvta_generic_to_shared(dst);
    asm volatile("cp.async.ca.shared.global [%0], [%1], 16, %2;\n"
                 :: "r"(d), "l"(src), "r"(sz) : "memory");
}
__device__ __forceinline__ void cp_async4(void* dst, const void* src, int sz) {
    unsigned d = (unsigned)__cvta_generic_to_shared(dst);
    asm volatile("cp.async.ca.shared.global [%0], [%1], 4, %2;\n"
                 :: "r"(d), "l"(src), "r"(sz) : "memory");
}
__device__ __forceinline__ void cp_commit() { asm volatile("cp.async.commit_group;\n" ::: "memory"); }
template<int M> __device__ __forceinline__ void cp_wait() {
    asm volatile("cp.async.wait_group %0;\n" :: "n"(M) : "memory");
}
__device__ __forceinline__ void dp8(int& a, uint4 x, uint4 y) {
    a = __dp4a((int)x.x, (int)y.x, a);
    a = __dp4a((int)x.y, (int)y.y, a);
    a = __dp4a((int)x.z, (int)y.z, a);
    a = __dp4a((int)x.w, (int)y.w, a);
}

// ---------------------------------------------------------------------------
// Kernel A: 2x2 avg-pool + int8 quantize of PREV only (query pooled in dist).
// Warp per half-res pixel: 480 blocks x 256 threads.
// ---------------------------------------------------------------------------
__global__ __launch_bounds__(256) void kern_down(const float* __restrict__ prev) {
    int pixel = blockIdx.x * 8 + (threadIdx.x >> 5);
    int lane  = threadIdx.x & 31;
    int r = pixel / hW, c = pixel - r*hW;
    int ch0 = lane * 4;

    float4 ys = make_float4(0.f,0.f,0.f,0.f);
    if (lane < 25) {
        int b = ((2*r)*WW + 2*c)*CC + ch0;
        float4 p0 = *(const float4*)&prev[b];
        float4 p1 = *(const float4*)&prev[b + CC];
        float4 p2 = *(const float4*)&prev[b + WW*CC];
        float4 p3 = *(const float4*)&prev[b + WW*CC + CC];
        ys = make_float4(0.25f*(p0.x+p1.x+p2.x+p3.x), 0.25f*(p0.y+p1.y+p2.y+p3.y),
                         0.25f*(p0.z+p1.z+p2.z+p3.z), 0.25f*(p0.w+p1.w+p2.w+p3.w));
    }
    float vy[4] = {ys.x, ys.y, ys.z, ys.w};
    int qy[4];
    int sy = 0;
    #pragma unroll
    for (int t = 0; t < 4; t++) {
        int b = __float2int_rn(vy[t] * QSCALE); b = max(-127, min(127, b));
        qy[t] = b;
        sy += b*b;
    }
    if (lane < 28) {
        *(char4*)&g_yq[pixel*CP8 + ch0] = make_char4((char)qy[0],(char)qy[1],(char)qy[2],(char)qy[3]);
    }
    sy = __reduce_add_sync(0xffffffffu, sy);
    if (lane == 0) g_syq[pixel] = sy;

    cudaTriggerProgrammaticLaunchCompletion();
}

// ---------------------------------------------------------------------------
// Kernel B v3: SINGLE-SHOT staging in 64KB dynamic smem. Pools x PRE-SYNC
// (overlaps kern_down via PDL), stages all 7 y-chunk arrays + sums with ONE
// cp.async commit/wait/sync, then runs the whole dp4a reduction barrier-free.
// Block = 2x4 pixel tile x 361 k. pix = tid&7, kg = tid>>3, 12 k per thread.
// NO register cap (caps spill: R6/R10/R11). Occupancy 2 blocks/SM, but the
// critical path loses 6 of 7 barrier/wait rounds vs the ping-pong version.
// ---------------------------------------------------------------------------
__global__ __launch_bounds__(256) void kern_dist(const float* __restrict__ query) {
    extern __shared__ __align__(16) unsigned char dsm[];
    uint4* ysBase = reinterpret_cast<uint4*>(dsm);            // 7 x [TROWS*TPITCH]
    int*   sy_s   = reinterpret_cast<int*>(dsm + DSM_SY);
    signed char* x_s = reinterpret_cast<signed char*>(dsm + DSM_XS);
    int*   sx_s   = reinterpret_cast<int*>(dsm + DSM_SXS);
    __shared__ int minp[8];

    int tid = threadIdx.x;
    int warp = tid >> 5;
    int lane = tid & 31;
    int pix = tid & 7;
    int kg  = tid >> 3;
    int pr  = pix >> 2, pc = pix & 3;
    int r0 = blockIdx.y * PR, c0 = blockIdx.x * PC;
    int r = r0 + pr, c = c0 + pc;

    // ---- PRE-SYNC: pool + quantize x for this block's 8 pixels (query input)
    {
        int wpr = warp >> 2, wpc = warp & 3;
        int rr = r0 + wpr, cc = c0 + wpc;
        int ch0 = lane * 4;
        float4 xs = make_float4(0.f,0.f,0.f,0.f);
        if (lane < 25) {
            int b = ((2*rr)*WW + 2*cc)*CC + ch0;
            float4 q0 = *(const float4*)&query[b];
            float4 q1 = *(const float4*)&query[b + CC];
            float4 q2 = *(const float4*)&query[b + WW*CC];
            float4 q3 = *(const float4*)&query[b + WW*CC + CC];
            xs = make_float4(0.25f*(q0.x+q1.x+q2.x+q3.x), 0.25f*(q0.y+q1.y+q2.y+q3.y),
                             0.25f*(q0.z+q1.z+q2.z+q3.z), 0.25f*(q0.w+q1.w+q2.w+q3.w));
        }
        float vx[4] = {xs.x, xs.y, xs.z, xs.w};
        int qx[4];
        int sx = 0;
        #pragma unroll
        for (int t = 0; t < 4; t++) {
            int a = __float2int_rn(vx[t] * QSCALE); a = max(-127, min(127, a));
            qx[t] = a;
            sx += a*a;
        }
        if (lane < 28)
            *(char4*)&x_s[warp*CP8 + ch0] = make_char4((char)qx[0],(char)qx[1],(char)qx[2],(char)qx[3]);
        sx = __reduce_add_sync(0xffffffffu, sx);
        if (lane == 0) sx_s[warp] = sx;
    }
    if (tid < 8) minp[tid] = 0x3F800000;   // 1.0f bits

    // pre-sync index math
    int soff[12];
    #pragma unroll
    for (int j = 0; j < 12; j++) {
        int k = kg + 32*j;
        int dy = k / KD;
        int dx = k - dy*KD;
        soff[j] = (pr + dy)*TPITCH + (pc + dx);
    }

    int dsti[2], pos[2], sz[2];
    long srcoff[2];
    bool has[2] = {true, (tid + 256) < TPOS};
    #pragma unroll
    for (int s = 0; s < 2; s++) {
        int i = tid + 256*s;
        int ii = has[s] ? i : 0;
        int row = ii / TCOLS, col = ii - row*TCOLS;
        int gr = r0 - MD + row, gc = c0 - MD + col;
        bool ok = (unsigned)gr < hH && (unsigned)gc < hW;
        pos[s]  = ii;
        dsti[s] = row*TPITCH + col;
        srcoff[s] = ok ? (long)(gr*hW + gc)*CP8 : 0;
        sz[s] = ok ? 16 : 0;
    }

    cudaGridDependencySynchronize();    // g_yq/g_syq ready

    // ---- single-shot stage: ALL 7 chunks + neighbor sums ----
    #pragma unroll
    for (int s = 0; s < 2; s++) if (has[s]) {
        const signed char* p = g_yq + srcoff[s];
        #pragma unroll
        for (int ci = 0; ci < 7; ci++)
            cp_async16(&ysBase[ci*(TROWS*TPITCH) + dsti[s]], p + ci*16, sz[s]);
        cp_async4(&sy_s[pos[s]], g_syq + (srcoff[s] / CP8), sz[s] ? 4 : 0);
    }
    cp_commit();
    cp_wait<0>();
    __syncthreads();        // the ONLY staging barrier

    const uint4* xg = reinterpret_cast<const uint4*>(&x_s[pix*CP8]);

    int acc[12];
    #pragma unroll
    for (int j = 0; j < 12; j++) acc[j] = 0;

    // ---- barrier-free compute over all 7 chunks ----
    #pragma unroll
    for (int ci = 0; ci < 7; ci++) {
        uint4 xa = xg[ci];
        const uint4* ys = &ysBase[ci*(TROWS*TPITCH)];
        #pragma unroll
        for (int j = 0; j < 11; j++) { uint4 ya = ys[soff[j]]; dp8(acc[j], xa, ya); }
        if (kg < 9)                  { uint4 ya = ys[soff[11]]; dp8(acc[11], xa, ya); }
    }

    // ---- epilogue: d -> (sigmoid-0.5)*2 -> g_S, plus per-pixel min ----
    int sx = sx_s[pix];
    float* Srow = &g_S[(r*hW + c)*K2P];
    float vmin = 1.0f;
    #pragma unroll
    for (int j = 0; j < 12; j++) {
        int k = kg + 32*j;
        if (k < K2P) {
            float val = 1.0f;   // PAD / out-of-range -> saturated sigmoid
            if (k < K2) {
                int dy = k / KD, dx = k - dy*KD;
                int sr = r + dy - MD, sc = c + dx - MD;
                if (sr >= 0 && sr < hH && sc >= 0 && sc < hW) {
                    int di = sx + sy_s[(pr + dy)*TCOLS + (pc + dx)] - 2*acc[j];
                    if (di < DSAT_I) {   // else saturates to exactly 1.0f
                        float d = (float)di * QSCALE2_INV;
                        float e = __expf(-d);
                        val = (1.0f - e) / (1.0f + e);   // == (sigmoid(d)-0.5)*2
                        vmin = fminf(vmin, val);
                    }
                }
            }
            Srow[k] = val;
        }
    }
    // per-pixel min reduction (positive floats: int compare == float compare)
    if (vmin < 1.0f) atomicMin(&minp[pix], __float_as_int(vmin));
    __syncthreads();
    if (tid < 8) g_minS[(r0 + (tid >> 2))*hW + c0 + (tid & 3)] = minp[tid];

    cudaTriggerProgrammaticLaunchCompletion();
}

// ---------------------------------------------------------------------------
// Kernel C: bilinear upsample + per-object masked min.
// Block = 16 output pixels of one row (512 threads, warp per pixel).
// BLOCK FAST PATH: if min over the block's 2x10 staged S rows (via g_minS)
// is 1.0, every lerp and masked min is exactly 1.0 -> write 1.0s and exit
// before any staging. Exact for any input; triggers ~always when saturated.
// ---------------------------------------------------------------------------
#define OPX 16
#define NW 10
#define LROWS KD            // 19
#define LCOLS (OPX + 2*MD)  // 34
template<int N>
__global__ __launch_bounds__(512) void kern_out(const int* __restrict__ labels,
                                                const int* __restrict__ gt,
                                                float* __restrict__ out) {
    __shared__ __align__(16) float Rv[NW][K2P];
    __shared__ int lab[LROWS*LCOLS];
    __shared__ int fastflag;

    int tid  = threadIdx.x;
    int warp = tid >> 5;
    int lane = tid & 31;
    int Y     = blockIdx.y;
    int Xbase = blockIdx.x * OPX;

    // ---- pre-sync: labels (input) + index math ----
    for (int i = tid; i < LROWS*LCOLS; i += 512) {
        int row = i / LCOLS, col = i - row*LCOLS;
        int gr = Y - MD + row, gc = Xbase - MD + col;
        lab[i] = (gr >= 0 && gr < HH && gc >= 0 && gc < WW) ? labels[gr*WW + gc] : -1;
    }

    const float sH = (float)(47.0/95.0);
    const float sW = (float)(79.0/159.0);
    float pH = (float)Y * sH;
    int loH = (int)floorf(pH); if (loH > hH-2) loH = hH-2;
    float fH = pH - (float)loH;
    int lo_min = (int)floorf((float)Xbase * sW);

    int X = Xbase + warp;
    float pW = (float)X * sW;
    int loW = (int)floorf(pW); if (loW > hW-2) loW = hW-2;
    float fW = pW - (float)loW;
    int wl = loW - lo_min;      // 0..8

    int gid[N];
    #pragma unroll
    for (int nn = 0; nn < N; nn++) gid[nn] = gt[nn];
    float mv[N];
    #pragma unroll
    for (int nn = 0; nn < N; nn++) mv[nn] = 1.0f;

    cudaGridDependencySynchronize();     // g_S / g_minS ready (PDL)

    // ---- block fast-path check: min over the 2 x NW relevant minS entries ----
    if (warp == 0) {
        float v = 1.0f;
        if (lane < 2*NW) {
            int rr = lane / NW, ccol = lane - rr*NW;
            int w = lo_min + ccol; if (w > hW-1) w = hW-1;
            v = __int_as_float(g_minS[(loH + rr)*hW + w]);
        }
        #pragma unroll
        for (int o = 16; o; o >>= 1) v = fminf(v, __shfl_xor_sync(0xffffffffu, v, o));
        if (lane == 0) fastflag = (v >= 1.0f);
    }
    __syncthreads();

    if (fastflag) {
        if (tid < OPX*N) {
            int p  = tid / N;
            int nn = tid - p*N;
            out[(Y*WW + Xbase + p)*N + nn] = 1.0f;
        }
        return;
    }

    // ---- slow path: stage with fused vertical lerp ----
    for (int i = tid; i < NW*(K2P/4); i += 512) {
        int ccol = i / (K2P/4);
        int qq   = i - ccol*(K2P/4);
        int w = lo_min + ccol; if (w > hW-1) w = hW-1;
        float4 a = ((const float4*)&g_S[(loH*hW + w)*K2P])[qq];
        float4 b = ((const float4*)&g_S[((loH+1)*hW + w)*K2P])[qq];
        float4 rr;
        rr.x = a.x + fH*(b.x - a.x);
        rr.y = a.y + fH*(b.y - a.y);
        rr.z = a.z + fH*(b.z - a.z);
        rr.w = a.w + fH*(b.w - a.w);
        ((float4*)Rv[0])[ccol*(K2P/4) + qq] = rr;
    }
    __syncthreads();

    // ---- per-warp horizontal lerp + masked min, with group saturation skip ----
    const float* Ra = Rv[wl];
    const float* Rb = Rv[wl+1];
    #pragma unroll
    for (int it = 0; it < 3; it++) {
        int q = lane + 32*it;
        if (q < 91) {
            float4 a = *(const float4*)&Ra[4*q];
            float4 b = *(const float4*)&Rb[4*q];
            float gm = fminf(fminf(fminf(a.x,a.y), fminf(a.z,a.w)),
                             fminf(fminf(b.x,b.y), fminf(b.z,b.w)));
            if (gm < 1.0f) {
                float av[4] = {a.x,a.y,a.z,a.w};
                float bv[4] = {b.x,b.y,b.z,b.w};
                #pragma unroll
                for (int t = 0; t < 4; t++) {
                    int k = 4*q + t;
                    if (k < K2) {
                        int dy = k / KD, dx = k - dy*KD;
                        int lbl = lab[dy*LCOLS + warp + dx];
                        float dval = av[t] + fW*(bv[t] - av[t]);
                        #pragma unroll
                        for (int nn = 0; nn < N; nn++)
                            if (lbl == gid[nn]) mv[nn] = fminf(mv[nn], dval);
                    }
                }
            }
        }
    }
    #pragma unroll
    for (int nn = 0; nn < N; nn++) {
        float v = mv[nn];
        #pragma unroll
        for (int o = 16; o; o >>= 1) v = fminf(v, __shfl_xor_sync(0xffffffffu, v, o));
        if (lane == 0) out[(Y*WW + X)*N + nn] = v;
    }
}

// ---------------------------------------------------------------------------
static void launch_pdl_raw(void* func, dim3 grid, dim3 block, void** args,
                           size_t dynSmem = 0) {
    cudaLaunchConfig_t cfg = {};
    cudaLaunchAttribute attr[1];
    attr[0].id = cudaLaunchAttributeProgrammaticStreamSerialization;
    attr[0].val.programmaticStreamSerializationAllowed = 1;
    cfg.gridDim  = grid;
    cfg.blockDim = block;
    cfg.dynamicSmemBytes = dynSmem;
    cfg.attrs = attr;
    cfg.numAttrs = 1;
    cfg.stream = 0;
    cudaLaunchKernelExC(&cfg, func, args);
}

template<int N>
static void launch_out_pdl(const int* labels, const int* gt, float* out) {
    void* args[] = {(void*)&labels, (void*)&gt, (void*)&out};
    launch_pdl_raw((void*)kern_out<N>, dim3(WW/OPX, HH, 1), dim3(512,1,1), args);
}

extern "C" void kernel_launch(void* const* d_in, const int* in_sizes, int n_in,
                              void* d_out, int out_size) {
    const float* prev   = (const float*)d_in[0];
    const float* query  = (const float*)d_in[1];
    const int*   labels = (const int*)d_in[2];
    const int*   gt     = (const int*)d_in[3];
    float* out = (float*)d_out;
    int n = out_size / (HH*WW);

    // opt in to >48KB dynamic smem for dist (idempotent, host-side, no alloc)
    cudaFuncSetAttribute((const void*)kern_dist,
                         cudaFuncAttributeMaxDynamicSharedMemorySize, DSM_TOT);

    kern_down<<<hH*hW/8, 256>>>(prev);            // 480 blocks

    {   // kern_dist with PDL + 64KB dynamic smem
        void* args[] = {(void*)&query};
        launch_pdl_raw((void*)kern_dist, dim3(hW/PC, hH/PR, 1), dim3(256,1,1),
                       args, DSM_TOT);
    }
    switch (n) {
        case 1: launch_out_pdl<1>(labels, gt, out); break;
        case 2: launch_out_pdl<2>(labels, gt, out); break;
        case 3: launch_out_pdl<3>(labels, gt, out); break;
        case 4: launch_out_pdl<4>(labels, gt, out); break;
        case 5: launch_out_pdl<5>(labels, gt, out); break;
        case 6: launch_out_pdl<6>(labels, gt, out); break;
        case 7: launch_out_pdl<7>(labels, gt, out); break;
        default: launch_out_pdl<8>(labels, gt, out); break;
    }
}